// round 1
// baseline (speedup 1.0000x reference)
#include <cuda_runtime.h>
#include <cuda_bf16.h>

// ---------------------------------------------------------------------------
// JointRetriveDeformHead — fp32 baseline, FFMA-roofline-shaped
//
// Pipeline:
//  k_pointnet : [64,2] blocks. Per-point MLP 3->64->128->256 (relu) with
//               maxpool folded into per-thread register maxima. Tiles of 32
//               points staged through smem; every GEMM uses 4-cols/thread
//               register tiling (LDS:FFMA = 1:4, coalesced float4 weights).
//  k_fc       : g @ Wf + bf for both encoders, plus T[b] = tgt[b] @ dec_W1[0:256]
//  k_dist     : variance-weighted distances (warp-per-source) + exact top-10
//               (iterative argmin with index tiebreak, matches jax top_k).
//  k_decode   : per (b,k): factored first layer (row-constant part computed
//               once), 256->256, ->6, proj@raw+def, mat@params -> output.
// ---------------------------------------------------------------------------

#define B_      64
#define S_      1024
#define D_      256
#define KRET    10
#define NPART   16
#define NPAR    96
#define PSRC3   1536

__device__ float g_pool[2 * B_ * D_];   // maxpooled features per encoder
__device__ float g_ret [B_ * D_];       // retrieval embedding (post-fc)
__device__ float g_T   [B_ * D_];       // tgt @ dec_W1[0:256,:]
__device__ int   g_idx [B_ * KRET];

// ---------------------------------------------------------------------------
// Kernel 1: PointNet encoders (both), grid (64, 2), 256 threads
// ---------------------------------------------------------------------------
#define TP 32   // points per tile

__global__ __launch_bounds__(256, 1)
void k_pointnet(const float* __restrict__ noc,
                const float* __restrict__ teW1, const float* __restrict__ teb1,
                const float* __restrict__ teW2, const float* __restrict__ teb2,
                const float* __restrict__ teW3, const float* __restrict__ teb3,
                const float* __restrict__ reW1, const float* __restrict__ reb1,
                const float* __restrict__ reW2, const float* __restrict__ reb2,
                const float* __restrict__ reW3, const float* __restrict__ reb3)
{
    const int b = blockIdx.x;
    const int enc = blockIdx.y;
    const float* W1 = enc ? reW1 : teW1; const float* b1 = enc ? reb1 : teb1;
    const float* W2 = enc ? reW2 : teW2; const float* b2 = enc ? reb2 : teb2;
    const float* W3 = enc ? reW3 : teW3; const float* b3 = enc ? reb3 : teb3;

    __shared__ float X[3][TP];       // transposed point coords
    __shared__ float H1[TP][64];
    __shared__ float H2[TP][128];
    __shared__ float red[4][256];

    const int t = threadIdx.x;

    // stage-B mapping (H1): 64 cols x 4 point-groups of 8
    const int colB = t & 63, pgB = t >> 6;
    // stage-C mapping (H2): 32x4 cols x 8 point-groups of 4
    const int c0C = (t & 31) * 4, pgC = t >> 5;
    // stage-D mapping (H3): 64x4 cols x 4 point-groups of 8
    const int c0D = (t & 63) * 4, pgD = t >> 6;

    const float w10 = W1[colB], w11 = W1[64 + colB], w12 = W1[128 + colB];
    const float bb1 = b1[colB];
    const float4 bb2 = *(const float4*)&b2[c0C];
    float b3v0 = b3[c0D], b3v1 = b3[c0D+1], b3v2 = b3[c0D+2], b3v3 = b3[c0D+3];

    float tmax0 = 0.f, tmax1 = 0.f, tmax2 = 0.f, tmax3 = 0.f;

    for (int tile = 0; tile < 1024 / TP; ++tile) {
        __syncthreads();   // protect H2/X from prior tile reads
        if (t < 96) {
            int c = t >> 5, p = t & 31;
            X[c][p] = noc[b * 3072 + c * 1024 + tile * TP + p];
        }
        __syncthreads();

        // ---- H1: 3 -> 64 ----
        #pragma unroll
        for (int pp = 0; pp < 8; ++pp) {
            int p = pgB * 8 + pp;
            float v = fmaf(X[0][p], w10, fmaf(X[1][p], w11, fmaf(X[2][p], w12, bb1)));
            H1[p][colB] = fmaxf(v, 0.f);
        }
        __syncthreads();

        // ---- H2: 64 -> 128 ----
        {
            float acc[4][4];
            #pragma unroll
            for (int p = 0; p < 4; ++p) {
                acc[p][0] = bb2.x; acc[p][1] = bb2.y; acc[p][2] = bb2.z; acc[p][3] = bb2.w;
            }
            #pragma unroll 8
            for (int k = 0; k < 64; ++k) {
                float4 w = *(const float4*)&W2[k * 128 + c0C];
                #pragma unroll
                for (int p = 0; p < 4; ++p) {
                    float x = H1[pgC * 4 + p][k];
                    acc[p][0] = fmaf(x, w.x, acc[p][0]);
                    acc[p][1] = fmaf(x, w.y, acc[p][1]);
                    acc[p][2] = fmaf(x, w.z, acc[p][2]);
                    acc[p][3] = fmaf(x, w.w, acc[p][3]);
                }
            }
            #pragma unroll
            for (int p = 0; p < 4; ++p) {
                float4 o;
                o.x = fmaxf(acc[p][0], 0.f); o.y = fmaxf(acc[p][1], 0.f);
                o.z = fmaxf(acc[p][2], 0.f); o.w = fmaxf(acc[p][3], 0.f);
                *(float4*)&H2[pgC * 4 + p][c0C] = o;
            }
        }
        __syncthreads();

        // ---- H3: 128 -> 256, relu, running max over points ----
        {
            float acc[8][4];
            #pragma unroll
            for (int p = 0; p < 8; ++p)
                acc[p][0] = acc[p][1] = acc[p][2] = acc[p][3] = 0.f;
            #pragma unroll 4
            for (int k = 0; k < 128; ++k) {
                float4 w = *(const float4*)&W3[k * 256 + c0D];
                #pragma unroll
                for (int p = 0; p < 8; ++p) {
                    float x = H2[pgD * 8 + p][k];
                    acc[p][0] = fmaf(x, w.x, acc[p][0]);
                    acc[p][1] = fmaf(x, w.y, acc[p][1]);
                    acc[p][2] = fmaf(x, w.z, acc[p][2]);
                    acc[p][3] = fmaf(x, w.w, acc[p][3]);
                }
            }
            #pragma unroll
            for (int p = 0; p < 8; ++p) {
                tmax0 = fmaxf(tmax0, fmaxf(acc[p][0] + b3v0, 0.f));
                tmax1 = fmaxf(tmax1, fmaxf(acc[p][1] + b3v1, 0.f));
                tmax2 = fmaxf(tmax2, fmaxf(acc[p][2] + b3v2, 0.f));
                tmax3 = fmaxf(tmax3, fmaxf(acc[p][3] + b3v3, 0.f));
            }
        }
    }

    // cross point-group max reduce (4 groups)
    red[pgD][c0D + 0] = tmax0;
    red[pgD][c0D + 1] = tmax1;
    red[pgD][c0D + 2] = tmax2;
    red[pgD][c0D + 3] = tmax3;
    __syncthreads();
    float m = fmaxf(fmaxf(red[0][t], red[1][t]), fmaxf(red[2][t], red[3][t]));
    g_pool[(enc * B_ + b) * D_ + t] = m;
}

// ---------------------------------------------------------------------------
// Kernel 2: final fc for both encoders + T = tgt @ dec_W1[0:256]
// ---------------------------------------------------------------------------
__global__ __launch_bounds__(256, 1)
void k_fc(const float* __restrict__ teWf, const float* __restrict__ tebf,
          const float* __restrict__ reWf, const float* __restrict__ rebf,
          const float* __restrict__ decW1)
{
    const int b = blockIdx.x, t = threadIdx.x;
    __shared__ float ste[256], sre[256], stgt[256];
    ste[t] = g_pool[b * D_ + t];
    sre[t] = g_pool[(B_ + b) * D_ + t];
    __syncthreads();

    float a = tebf[t], r = rebf[t];
    #pragma unroll 8
    for (int i = 0; i < 256; ++i) {
        a = fmaf(ste[i], teWf[i * 256 + t], a);
        r = fmaf(sre[i], reWf[i * 256 + t], r);
    }
    g_ret[b * D_ + t] = r;
    stgt[t] = a;
    __syncthreads();

    float tv = 0.f;
    #pragma unroll 8
    for (int i = 0; i < 256; ++i)
        tv = fmaf(stgt[i], decW1[i * 256 + t], tv);
    g_T[b * D_ + t] = tv;
}

// ---------------------------------------------------------------------------
// Kernel 3: variance-weighted distances + exact top-10 (jax tiebreak)
// ---------------------------------------------------------------------------
__global__ __launch_bounds__(256, 1)
void k_dist(const float* __restrict__ rsc, const float* __restrict__ var)
{
    const int b = blockIdx.x, t = threadIdx.x;
    const int lane = t & 31, w = t >> 5;
    __shared__ float rets[256];
    __shared__ float d[1024];
    __shared__ float sval[256];
    __shared__ int   sidx[256];

    rets[t] = g_ret[b * D_ + t];
    __syncthreads();

    for (int s = w; s < S_; s += 8) {
        float p = 0.f;
        #pragma unroll
        for (int q = 0; q < 2; ++q) {
            int k = lane * 8 + q * 4;
            float4 v  = *(const float4*)&var[s * 256 + k];
            float4 rc = *(const float4*)&rsc[s * 256 + k];
            float d0 = rets[k]     - rc.x;
            float d1 = rets[k + 1] - rc.y;
            float d2 = rets[k + 2] - rc.z;
            float d3 = rets[k + 3] - rc.w;
            p = fmaf(v.x, d0 * d0, p);
            p = fmaf(v.y, d1 * d1, p);
            p = fmaf(v.z, d2 * d2, p);
            p = fmaf(v.w, d3 * d3, p);
        }
        #pragma unroll
        for (int off = 16; off > 0; off >>= 1)
            p += __shfl_xor_sync(0xffffffffu, p, off);
        if (lane == 0) d[s] = p;
    }
    __syncthreads();

    for (int it = 0; it < KRET; ++it) {
        float bv = 1e30f; int bi = S_;
        #pragma unroll
        for (int q = 0; q < 4; ++q) {
            int s = q * 256 + t;
            float v = d[s];
            if (v < bv || (v == bv && s < bi)) { bv = v; bi = s; }
        }
        sval[t] = bv; sidx[t] = bi;
        __syncthreads();
        for (int off = 128; off > 0; off >>= 1) {
            if (t < off) {
                float v2 = sval[t + off]; int i2 = sidx[t + off];
                if (v2 < sval[t] || (v2 == sval[t] && i2 < sidx[t])) {
                    sval[t] = v2; sidx[t] = i2;
                }
            }
            __syncthreads();
        }
        if (t == 0) {
            g_idx[b * KRET + it] = sidx[0];
            d[sidx[0]] = 1e30f;
        }
        __syncthreads();
    }
}

// ---------------------------------------------------------------------------
// Kernel 4: decoder + projection + deformation. grid 640, 256 threads.
// First layer factored: H1[p][j] = relu(T[b][j] + b1[j] + sc.W1mid[:,j]
//                                        + part[p].W1tail[:,j])
// ---------------------------------------------------------------------------
__global__ __launch_bounds__(256, 1)
void k_decode(const float* __restrict__ src_codes,
              const float* __restrict__ part_latent,
              const float* __restrict__ decW1, const float* __restrict__ decb1,
              const float* __restrict__ decW2, const float* __restrict__ decb2,
              const float* __restrict__ decW3, const float* __restrict__ decb3,
              const float* __restrict__ proj,  const float* __restrict__ defp,
              const float* __restrict__ mat,   float* __restrict__ out)
{
    const int bk = blockIdx.x;
    const int b = bk / KRET;
    const int t = threadIdx.x;
    const int s = g_idx[bk];

    __shared__ float sc[256];
    __shared__ float part[NPART][32];
    __shared__ float H1[NPART][256];
    __shared__ float H2[NPART][256];
    __shared__ float raw[NPAR];
    __shared__ float par[NPAR];

    sc[t] = src_codes[s * 256 + t];
    ((float*)part)[t]       = part_latent[s * (NPART * 32) + t];
    ((float*)part)[t + 256] = part_latent[s * (NPART * 32) + t + 256];
    __syncthreads();

    // ---- factored first layer ----
    {
        float c = g_T[b * D_ + t] + decb1[t];
        #pragma unroll 8
        for (int i = 0; i < 256; ++i)
            c = fmaf(sc[i], decW1[(256 + i) * 256 + t], c);
        float wt[32];
        #pragma unroll
        for (int i = 0; i < 32; ++i)
            wt[i] = decW1[(512 + i) * 256 + t];
        #pragma unroll
        for (int p = 0; p < NPART; ++p) {
            float v = c;
            #pragma unroll
            for (int i = 0; i < 32; ++i)
                v = fmaf(part[p][i], wt[i], v);
            H1[p][t] = fmaxf(v, 0.f);
        }
    }
    __syncthreads();

    // ---- H2: 256 -> 256, 4 cols x 4 points per thread ----
    {
        const int c0 = (t & 63) * 4, pg = t >> 6;
        float acc[4][4];
        float4 bb = *(const float4*)&decb2[c0];
        #pragma unroll
        for (int p = 0; p < 4; ++p) {
            acc[p][0] = bb.x; acc[p][1] = bb.y; acc[p][2] = bb.z; acc[p][3] = bb.w;
        }
        #pragma unroll 4
        for (int k = 0; k < 256; ++k) {
            float4 w = *(const float4*)&decW2[k * 256 + c0];
            #pragma unroll
            for (int p = 0; p < 4; ++p) {
                float x = H1[pg * 4 + p][k];
                acc[p][0] = fmaf(x, w.x, acc[p][0]);
                acc[p][1] = fmaf(x, w.y, acc[p][1]);
                acc[p][2] = fmaf(x, w.z, acc[p][2]);
                acc[p][3] = fmaf(x, w.w, acc[p][3]);
            }
        }
        #pragma unroll
        for (int p = 0; p < 4; ++p) {
            float4 o;
            o.x = fmaxf(acc[p][0], 0.f); o.y = fmaxf(acc[p][1], 0.f);
            o.z = fmaxf(acc[p][2], 0.f); o.w = fmaxf(acc[p][3], 0.f);
            *(float4*)&H2[pg * 4 + p][c0] = o;
        }
    }
    __syncthreads();

    // ---- raw = H2 @ W3 + b3  (16x6 = 96 outputs) ----
    if (t < NPAR) {
        const int p = t / 6, o = t % 6;
        float v = decb3[o];
        #pragma unroll 8
        for (int k = 0; k < 256; ++k)
            v = fmaf(H2[p][k], decW3[k * 6 + o], v);
        raw[t] = v;
    }
    __syncthreads();

    // ---- params = proj[s] @ raw + def[s] ----
    if (t < NPAR) {
        float v = defp[s * NPAR + t];
        const float* pr = proj + (size_t)s * NPAR * NPAR + t * NPAR;
        #pragma unroll 8
        for (int j = 0; j < NPAR; ++j)
            v = fmaf(pr[j], raw[j], v);
        par[t] = v;
    }
    __syncthreads();

    // ---- pts = mat[s] @ params ----
    const float* mb = mat + (size_t)s * PSRC3 * NPAR;
    float* ob = out + (size_t)bk * PSRC3;
    #pragma unroll
    for (int rr = 0; rr < 6; ++rr) {
        int r = rr * 256 + t;
        const float4* mr = (const float4*)(mb + (size_t)r * NPAR);
        float v = 0.f;
        #pragma unroll
        for (int j4 = 0; j4 < 24; ++j4) {
            float4 m4 = mr[j4];
            v = fmaf(m4.x, par[j4 * 4 + 0], v);
            v = fmaf(m4.y, par[j4 * 4 + 1], v);
            v = fmaf(m4.z, par[j4 * 4 + 2], v);
            v = fmaf(m4.w, par[j4 * 4 + 3], v);
        }
        ob[r] = v;
    }
}

// ---------------------------------------------------------------------------
extern "C" void kernel_launch(void* const* d_in, const int* in_sizes, int n_in,
                              void* d_out, int out_size)
{
    const float* noc  = (const float*)d_in[0];
    const float* teW1 = (const float*)d_in[1];  const float* teb1 = (const float*)d_in[2];
    const float* teW2 = (const float*)d_in[3];  const float* teb2 = (const float*)d_in[4];
    const float* teW3 = (const float*)d_in[5];  const float* teb3 = (const float*)d_in[6];
    const float* teWf = (const float*)d_in[7];  const float* tebf = (const float*)d_in[8];
    const float* reW1 = (const float*)d_in[9];  const float* reb1 = (const float*)d_in[10];
    const float* reW2 = (const float*)d_in[11]; const float* reb2 = (const float*)d_in[12];
    const float* reW3 = (const float*)d_in[13]; const float* reb3 = (const float*)d_in[14];
    const float* reWf = (const float*)d_in[15]; const float* rebf = (const float*)d_in[16];
    const float* decW1 = (const float*)d_in[17]; const float* decb1 = (const float*)d_in[18];
    const float* decW2 = (const float*)d_in[19]; const float* decb2 = (const float*)d_in[20];
    const float* decW3 = (const float*)d_in[21]; const float* decb3 = (const float*)d_in[22];
    const float* ret_src = (const float*)d_in[23];
    const float* src_codes = (const float*)d_in[24];
    const float* src_var = (const float*)d_in[25];
    const float* part_latent = (const float*)d_in[26];
    const float* defp = (const float*)d_in[27];
    const float* proj = (const float*)d_in[28];
    const float* mat  = (const float*)d_in[29];
    float* out = (float*)d_out;

    dim3 g1(B_, 2);
    k_pointnet<<<g1, 256>>>(noc,
                            teW1, teb1, teW2, teb2, teW3, teb3,
                            reW1, reb1, reW2, reb2, reW3, reb3);
    k_fc<<<B_, 256>>>(teWf, tebf, reWf, rebf, decW1);
    k_dist<<<B_, 256>>>(ret_src, src_var);
    k_decode<<<B_ * KRET, 256>>>(src_codes, part_latent,
                                 decW1, decb1, decW2, decb2, decW3, decb3,
                                 proj, defp, mat, out);
}

// round 2
// speedup vs baseline: 1.2829x; 1.2829x over previous
#include <cuda_runtime.h>
#include <cuda_bf16.h>

// ---------------------------------------------------------------------------
// JointRetriveDeformHead — round 2
//  * PointNet H2/H3 use packed fma.rn.f32x2 (FFMA2): channel-major smem with
//    point-pairs contiguous -> packed operand = one LDS.64 broadcast.
//  * PointNet split into 4 point-quarters (grid 64x2x4), partial max reduced
//    in k_fc -> all 148 SMs used, 2 CTAs/SM.
//  * Decoder split: k_decode_mlp (params only, 3 CTAs/SM) + k_deform
//    (mat @ params, high-occupancy, L2-BW bound).
// ---------------------------------------------------------------------------

#define B_      64
#define S_      1024
#define D_      256
#define KRET    10
#define NPART   16
#define NPAR    96
#define PSRC3   1536
#define NQ      4        // point quarters in pointnet

__device__ float g_pool[NQ * 2 * B_ * D_];  // partial maxima [q][enc][b][d]
__device__ float g_ret [B_ * D_];
__device__ float g_T   [B_ * D_];
__device__ int   g_idx [B_ * KRET];
__device__ float g_par [B_ * KRET * NPAR];

typedef unsigned long long u64;

__device__ __forceinline__ u64 pk(float lo, float hi) {
    u64 r; asm("mov.b64 %0,{%1,%2};" : "=l"(r) : "f"(lo), "f"(hi)); return r;
}
__device__ __forceinline__ void upk(u64 v, float& lo, float& hi) {
    asm("mov.b64 {%0,%1},%2;" : "=f"(lo), "=f"(hi) : "l"(v));
}
__device__ __forceinline__ u64 fma2(u64 a, u64 b, u64 c) {
    u64 d; asm("fma.rn.f32x2 %0,%1,%2,%3;" : "=l"(d) : "l"(a), "l"(b), "l"(c)); return d;
}

// ---------------------------------------------------------------------------
// Kernel 1: PointNet encoders, grid (64, 2, NQ), 256 threads, 2 CTAs/SM.
// Each block handles 256 points (8 tiles of 32).
// ---------------------------------------------------------------------------
#define TP 32

__global__ __launch_bounds__(256, 2)
void k_pointnet(const float* __restrict__ noc,
                const float* __restrict__ teW1, const float* __restrict__ teb1,
                const float* __restrict__ teW2, const float* __restrict__ teb2,
                const float* __restrict__ teW3, const float* __restrict__ teb3,
                const float* __restrict__ reW1, const float* __restrict__ reb1,
                const float* __restrict__ reW2, const float* __restrict__ reb2,
                const float* __restrict__ reW3, const float* __restrict__ reb3)
{
    const int b = blockIdx.x;
    const int enc = blockIdx.y;
    const int qz = blockIdx.z;
    const float* W1 = enc ? reW1 : teW1; const float* b1 = enc ? reb1 : teb1;
    const float* W2 = enc ? reW2 : teW2; const float* b2 = enc ? reb2 : teb2;
    const float* W3 = enc ? reW3 : teW3; const float* b3 = enc ? reb3 : teb3;

    __shared__ __align__(16) float X[3][TP];
    __shared__ __align__(16) float H1c[64][34];    // [channel][point], pad 34
    __shared__ __align__(16) float H2c[128][34];
    __shared__ __align__(16) float red[4][256];

    const int t = threadIdx.x;

    const int colB = t & 63, pgB = t >> 6;          // H1: 64 ch x 4 pgroups of 8
    const int c0C = (t & 31) * 4, pgC = t >> 5;     // H2: 32x4 ch x 8 pgroups of 4
    const int c0D = (t & 63) * 4, pgD = t >> 6;     // H3: 64x4 ch x 4 pgroups of 8

    const float w10 = W1[colB], w11 = W1[64 + colB], w12 = W1[128 + colB];
    const float bb1 = b1[colB];
    const float4 bb2 = *(const float4*)&b2[c0C];
    const u64 bb2p[4] = { pk(bb2.x, bb2.x), pk(bb2.y, bb2.y),
                          pk(bb2.z, bb2.z), pk(bb2.w, bb2.w) };
    const float b3v[4] = { b3[c0D], b3[c0D+1], b3[c0D+2], b3[c0D+3] };

    float tmax[4] = {0.f, 0.f, 0.f, 0.f};

    for (int tile = 0; tile < 256 / TP; ++tile) {
        __syncthreads();
        if (t < 96) {
            int c = t >> 5, p = t & 31;
            X[c][p] = noc[b * 3072 + c * 1024 + qz * 256 + tile * TP + p];
        }
        __syncthreads();

        // ---- H1: 3 -> 64 (scalar; tiny) ----
        {
            float v[8];
            #pragma unroll
            for (int pp = 0; pp < 8; ++pp) {
                int p = pgB * 8 + pp;
                float h = fmaf(X[0][p], w10, fmaf(X[1][p], w11, fmaf(X[2][p], w12, bb1)));
                v[pp] = fmaxf(h, 0.f);
            }
            #pragma unroll
            for (int q = 0; q < 4; ++q)
                *(u64*)&H1c[colB][pgB * 8 + 2 * q] = pk(v[2*q], v[2*q+1]);
        }
        __syncthreads();

        // ---- H2: 64 -> 128, f32x2 (4 points = 2 pairs x 4 cols) ----
        {
            u64 acc[2][4];
            #pragma unroll
            for (int q = 0; q < 2; ++q)
                #pragma unroll
                for (int j = 0; j < 4; ++j) acc[q][j] = bb2p[j];
            #pragma unroll 4
            for (int k = 0; k < 64; ++k) {
                u64 x0 = *(const u64*)&H1c[k][pgC * 4];
                u64 x1 = *(const u64*)&H1c[k][pgC * 4 + 2];
                float4 w = *(const float4*)&W2[k * 128 + c0C];
                u64 wp0 = pk(w.x, w.x), wp1 = pk(w.y, w.y);
                u64 wp2 = pk(w.z, w.z), wp3 = pk(w.w, w.w);
                acc[0][0] = fma2(x0, wp0, acc[0][0]);
                acc[0][1] = fma2(x0, wp1, acc[0][1]);
                acc[0][2] = fma2(x0, wp2, acc[0][2]);
                acc[0][3] = fma2(x0, wp3, acc[0][3]);
                acc[1][0] = fma2(x1, wp0, acc[1][0]);
                acc[1][1] = fma2(x1, wp1, acc[1][1]);
                acc[1][2] = fma2(x1, wp2, acc[1][2]);
                acc[1][3] = fma2(x1, wp3, acc[1][3]);
            }
            #pragma unroll
            for (int j = 0; j < 4; ++j) {
                #pragma unroll
                for (int q = 0; q < 2; ++q) {
                    float lo, hi; upk(acc[q][j], lo, hi);
                    lo = fmaxf(lo, 0.f); hi = fmaxf(hi, 0.f);
                    *(u64*)&H2c[c0C + j][pgC * 4 + 2 * q] = pk(lo, hi);
                }
            }
        }
        __syncthreads();

        // ---- H3: 128 -> 256, f32x2, relu+bias+running max ----
        {
            u64 acc[4][4];
            #pragma unroll
            for (int q = 0; q < 4; ++q)
                #pragma unroll
                for (int j = 0; j < 4; ++j) acc[q][j] = 0ull;
            #pragma unroll 2
            for (int k = 0; k < 128; ++k) {
                u64 x0 = *(const u64*)&H2c[k][pgD * 8];
                u64 x1 = *(const u64*)&H2c[k][pgD * 8 + 2];
                u64 x2 = *(const u64*)&H2c[k][pgD * 8 + 4];
                u64 x3 = *(const u64*)&H2c[k][pgD * 8 + 6];
                float4 w = *(const float4*)&W3[k * 256 + c0D];
                u64 wp0 = pk(w.x, w.x), wp1 = pk(w.y, w.y);
                u64 wp2 = pk(w.z, w.z), wp3 = pk(w.w, w.w);
                acc[0][0] = fma2(x0, wp0, acc[0][0]);
                acc[0][1] = fma2(x0, wp1, acc[0][1]);
                acc[0][2] = fma2(x0, wp2, acc[0][2]);
                acc[0][3] = fma2(x0, wp3, acc[0][3]);
                acc[1][0] = fma2(x1, wp0, acc[1][0]);
                acc[1][1] = fma2(x1, wp1, acc[1][1]);
                acc[1][2] = fma2(x1, wp2, acc[1][2]);
                acc[1][3] = fma2(x1, wp3, acc[1][3]);
                acc[2][0] = fma2(x2, wp0, acc[2][0]);
                acc[2][1] = fma2(x2, wp1, acc[2][1]);
                acc[2][2] = fma2(x2, wp2, acc[2][2]);
                acc[2][3] = fma2(x2, wp3, acc[2][3]);
                acc[3][0] = fma2(x3, wp0, acc[3][0]);
                acc[3][1] = fma2(x3, wp1, acc[3][1]);
                acc[3][2] = fma2(x3, wp2, acc[3][2]);
                acc[3][3] = fma2(x3, wp3, acc[3][3]);
            }
            #pragma unroll
            for (int q = 0; q < 4; ++q) {
                #pragma unroll
                for (int j = 0; j < 4; ++j) {
                    float lo, hi; upk(acc[q][j], lo, hi);
                    tmax[j] = fmaxf(tmax[j], fmaxf(lo + b3v[j], 0.f));
                    tmax[j] = fmaxf(tmax[j], fmaxf(hi + b3v[j], 0.f));
                }
            }
        }
    }

    #pragma unroll
    for (int j = 0; j < 4; ++j) red[pgD][c0D + j] = tmax[j];
    __syncthreads();
    float m = fmaxf(fmaxf(red[0][t], red[1][t]), fmaxf(red[2][t], red[3][t]));
    g_pool[((qz * 2 + enc) * B_ + b) * D_ + t] = m;
}

// ---------------------------------------------------------------------------
// Kernel 2: reduce quarters + final fc + T = tgt @ dec_W1[0:256]
// ---------------------------------------------------------------------------
__global__ __launch_bounds__(256, 1)
void k_fc(const float* __restrict__ teWf, const float* __restrict__ tebf,
          const float* __restrict__ reWf, const float* __restrict__ rebf,
          const float* __restrict__ decW1)
{
    const int b = blockIdx.x, t = threadIdx.x;
    __shared__ float ste[256], sre[256], stgt[256];
    float mte = 0.f, mre = 0.f;
    #pragma unroll
    for (int q = 0; q < NQ; ++q) {
        mte = fmaxf(mte, g_pool[((q * 2 + 0) * B_ + b) * D_ + t]);
        mre = fmaxf(mre, g_pool[((q * 2 + 1) * B_ + b) * D_ + t]);
    }
    ste[t] = mte; sre[t] = mre;
    __syncthreads();

    float a = tebf[t], r = rebf[t];
    #pragma unroll 8
    for (int i = 0; i < 256; ++i) {
        a = fmaf(ste[i], teWf[i * 256 + t], a);
        r = fmaf(sre[i], reWf[i * 256 + t], r);
    }
    g_ret[b * D_ + t] = r;
    stgt[t] = a;
    __syncthreads();

    float tv = 0.f;
    #pragma unroll 8
    for (int i = 0; i < 256; ++i)
        tv = fmaf(stgt[i], decW1[i * 256 + t], tv);
    g_T[b * D_ + t] = tv;
}

// ---------------------------------------------------------------------------
// Kernel 3: variance-weighted distances + exact top-10
// ---------------------------------------------------------------------------
__global__ __launch_bounds__(256, 1)
void k_dist(const float* __restrict__ rsc, const float* __restrict__ var)
{
    const int b = blockIdx.x, t = threadIdx.x;
    const int lane = t & 31, w = t >> 5;
    __shared__ float rets[256];
    __shared__ float d[1024];
    __shared__ float sval[256];
    __shared__ int   sidx[256];

    rets[t] = g_ret[b * D_ + t];
    __syncthreads();

    for (int s = w; s < S_; s += 8) {
        float p = 0.f;
        #pragma unroll
        for (int q = 0; q < 2; ++q) {
            int k = lane * 8 + q * 4;
            float4 v  = *(const float4*)&var[s * 256 + k];
            float4 rc = *(const float4*)&rsc[s * 256 + k];
            float d0 = rets[k]     - rc.x;
            float d1 = rets[k + 1] - rc.y;
            float d2 = rets[k + 2] - rc.z;
            float d3 = rets[k + 3] - rc.w;
            p = fmaf(v.x, d0 * d0, p);
            p = fmaf(v.y, d1 * d1, p);
            p = fmaf(v.z, d2 * d2, p);
            p = fmaf(v.w, d3 * d3, p);
        }
        #pragma unroll
        for (int off = 16; off > 0; off >>= 1)
            p += __shfl_xor_sync(0xffffffffu, p, off);
        if (lane == 0) d[s] = p;
    }
    __syncthreads();

    for (int it = 0; it < KRET; ++it) {
        float bv = 1e30f; int bi = S_;
        #pragma unroll
        for (int q = 0; q < 4; ++q) {
            int s = q * 256 + t;
            float v = d[s];
            if (v < bv || (v == bv && s < bi)) { bv = v; bi = s; }
        }
        sval[t] = bv; sidx[t] = bi;
        __syncthreads();
        for (int off = 128; off > 0; off >>= 1) {
            if (t < off) {
                float v2 = sval[t + off]; int i2 = sidx[t + off];
                if (v2 < sval[t] || (v2 == sval[t] && i2 < sidx[t])) {
                    sval[t] = v2; sidx[t] = i2;
                }
            }
            __syncthreads();
        }
        if (t == 0) {
            g_idx[b * KRET + it] = sidx[0];
            d[sidx[0]] = 1e30f;
        }
        __syncthreads();
    }
}

// ---------------------------------------------------------------------------
// Kernel 4: decoder MLP -> params[96] per (b,k). 3 CTAs/SM.
// ---------------------------------------------------------------------------
__global__ __launch_bounds__(256, 3)
void k_decode_mlp(const float* __restrict__ src_codes,
                  const float* __restrict__ part_latent,
                  const float* __restrict__ decW1, const float* __restrict__ decb1,
                  const float* __restrict__ decW2, const float* __restrict__ decb2,
                  const float* __restrict__ decW3, const float* __restrict__ decb3,
                  const float* __restrict__ proj,  const float* __restrict__ defp)
{
    const int bk = blockIdx.x;
    const int b = bk / KRET;
    const int t = threadIdx.x;
    const int s = g_idx[bk];

    __shared__ float sc[256];
    __shared__ float part[NPART][32];
    __shared__ float Hc[256];
    __shared__ float H1s[256][17];   // [k][part]
    __shared__ float H2s[256][17];
    __shared__ float raw[NPAR];

    sc[t] = src_codes[s * 256 + t];
    ((float*)part)[t]       = part_latent[s * (NPART * 32) + t];
    ((float*)part)[t + 256] = part_latent[s * (NPART * 32) + t + 256];
    __syncthreads();

    // ---- shared column term: Hc[t] = T[b][t] + b1[t] + sc . W1mid[:,t] ----
    {
        float c = g_T[b * D_ + t] + decb1[t];
        #pragma unroll 8
        for (int i = 0; i < 256; ++i)
            c = fmaf(sc[i], decW1[(256 + i) * 256 + t], c);
        Hc[t] = c;
    }
    __syncthreads();

    const int c0 = (t & 63) * 4, pg = t >> 6;   // 4 cols x 4 parts per thread

    // ---- first layer part contribution: H1[p][c] = relu(Hc[c] + part[p].W1tail[:,c]) ----
    {
        float acc[4][4];
        float h0 = Hc[c0], h1 = Hc[c0+1], h2 = Hc[c0+2], h3 = Hc[c0+3];
        #pragma unroll
        for (int p = 0; p < 4; ++p) {
            acc[p][0] = h0; acc[p][1] = h1; acc[p][2] = h2; acc[p][3] = h3;
        }
        #pragma unroll 4
        for (int k = 0; k < 32; ++k) {
            float4 w = *(const float4*)&decW1[(512 + k) * 256 + c0];
            #pragma unroll
            for (int p = 0; p < 4; ++p) {
                float x = part[pg * 4 + p][k];
                acc[p][0] = fmaf(x, w.x, acc[p][0]);
                acc[p][1] = fmaf(x, w.y, acc[p][1]);
                acc[p][2] = fmaf(x, w.z, acc[p][2]);
                acc[p][3] = fmaf(x, w.w, acc[p][3]);
            }
        }
        #pragma unroll
        for (int j = 0; j < 4; ++j)
            #pragma unroll
            for (int p = 0; p < 4; ++p)
                H1s[c0 + j][pg * 4 + p] = fmaxf(acc[p][j], 0.f);
    }
    __syncthreads();

    // ---- H2: 256 -> 256 ----
    {
        float acc[4][4];
        float4 bb = *(const float4*)&decb2[c0];
        #pragma unroll
        for (int p = 0; p < 4; ++p) {
            acc[p][0] = bb.x; acc[p][1] = bb.y; acc[p][2] = bb.z; acc[p][3] = bb.w;
        }
        #pragma unroll 4
        for (int k = 0; k < 256; ++k) {
            float4 w = *(const float4*)&decW2[k * 256 + c0];
            #pragma unroll
            for (int p = 0; p < 4; ++p) {
                float x = H1s[k][pg * 4 + p];
                acc[p][0] = fmaf(x, w.x, acc[p][0]);
                acc[p][1] = fmaf(x, w.y, acc[p][1]);
                acc[p][2] = fmaf(x, w.z, acc[p][2]);
                acc[p][3] = fmaf(x, w.w, acc[p][3]);
            }
        }
        #pragma unroll
        for (int j = 0; j < 4; ++j)
            #pragma unroll
            for (int p = 0; p < 4; ++p)
                H2s[c0 + j][pg * 4 + p] = fmaxf(acc[p][j], 0.f);
    }
    __syncthreads();

    // ---- raw = H2 @ W3 + b3 ----
    if (t < NPAR) {
        const int p = t / 6, o = t % 6;
        float v = decb3[o];
        #pragma unroll 8
        for (int k = 0; k < 256; ++k)
            v = fmaf(H2s[k][p], decW3[k * 6 + o], v);
        raw[t] = v;
    }
    __syncthreads();

    // ---- params = proj[s] @ raw + def[s] -> g_par ----
    if (t < NPAR) {
        float v = defp[s * NPAR + t];
        const float* pr = proj + (size_t)s * NPAR * NPAR + t * NPAR;
        #pragma unroll 8
        for (int j = 0; j < NPAR; ++j)
            v = fmaf(pr[j], raw[j], v);
        g_par[bk * NPAR + t] = v;
    }
}

// ---------------------------------------------------------------------------
// Kernel 5: deformation pts = mat[s] @ params. High occupancy, L2-BW bound.
// ---------------------------------------------------------------------------
__global__ __launch_bounds__(256)
void k_deform(const float* __restrict__ mat, float* __restrict__ out)
{
    const int bk = blockIdx.x;
    const int t = threadIdx.x;
    const int s = g_idx[bk];
    __shared__ float par[NPAR];
    if (t < NPAR) par[t] = g_par[bk * NPAR + t];
    __syncthreads();

    const float* mb = mat + (size_t)s * PSRC3 * NPAR;
    float* ob = out + (size_t)bk * PSRC3;
    #pragma unroll
    for (int rr = 0; rr < 6; ++rr) {
        int r = rr * 256 + t;
        const float4* mr = (const float4*)(mb + (size_t)r * NPAR);
        float v = 0.f;
        #pragma unroll
        for (int j4 = 0; j4 < 24; ++j4) {
            float4 m4 = mr[j4];
            v = fmaf(m4.x, par[j4 * 4 + 0], v);
            v = fmaf(m4.y, par[j4 * 4 + 1], v);
            v = fmaf(m4.z, par[j4 * 4 + 2], v);
            v = fmaf(m4.w, par[j4 * 4 + 3], v);
        }
        ob[r] = v;
    }
}

// ---------------------------------------------------------------------------
extern "C" void kernel_launch(void* const* d_in, const int* in_sizes, int n_in,
                              void* d_out, int out_size)
{
    const float* noc  = (const float*)d_in[0];
    const float* teW1 = (const float*)d_in[1];  const float* teb1 = (const float*)d_in[2];
    const float* teW2 = (const float*)d_in[3];  const float* teb2 = (const float*)d_in[4];
    const float* teW3 = (const float*)d_in[5];  const float* teb3 = (const float*)d_in[6];
    const float* teWf = (const float*)d_in[7];  const float* tebf = (const float*)d_in[8];
    const float* reW1 = (const float*)d_in[9];  const float* reb1 = (const float*)d_in[10];
    const float* reW2 = (const float*)d_in[11]; const float* reb2 = (const float*)d_in[12];
    const float* reW3 = (const float*)d_in[13]; const float* reb3 = (const float*)d_in[14];
    const float* reWf = (const float*)d_in[15]; const float* rebf = (const float*)d_in[16];
    const float* decW1 = (const float*)d_in[17]; const float* decb1 = (const float*)d_in[18];
    const float* decW2 = (const float*)d_in[19]; const float* decb2 = (const float*)d_in[20];
    const float* decW3 = (const float*)d_in[21]; const float* decb3 = (const float*)d_in[22];
    const float* ret_src = (const float*)d_in[23];
    const float* src_codes = (const float*)d_in[24];
    const float* src_var = (const float*)d_in[25];
    const float* part_latent = (const float*)d_in[26];
    const float* defp = (const float*)d_in[27];
    const float* proj = (const float*)d_in[28];
    const float* mat  = (const float*)d_in[29];
    float* out = (float*)d_out;

    dim3 g1(B_, 2, NQ);
    k_pointnet<<<g1, 256>>>(noc,
                            teW1, teb1, teW2, teb2, teW3, teb3,
                            reW1, reb1, reW2, reb2, reW3, reb3);
    k_fc<<<B_, 256>>>(teWf, tebf, reWf, rebf, decW1);
    k_dist<<<B_, 256>>>(ret_src, src_var);
    k_decode_mlp<<<B_ * KRET, 256>>>(src_codes, part_latent,
                                     decW1, decb1, decW2, decb2, decW3, decb3,
                                     proj, defp);
    k_deform<<<B_ * KRET, 256>>>(mat, out);
}

// round 3
// speedup vs baseline: 1.4162x; 1.1040x over previous
#include <cuda_runtime.h>
#include <cuda_bf16.h>

// ---------------------------------------------------------------------------
// JointRetriveDeformHead — round 3
//  * NEW k_pre: SC1[s] = src_codes[s]·W1mid + b1, P1[s][p] = part[s,p]·W1tail
//    for ALL 1024 sources (s-only terms hoisted out of the per-(b,k) decoder).
//  * k_decode_mlp: layer-1 is now load+add+relu; H2 uses f32x2 over part
//    pairs; 4 CTAs/SM.
//  * k_pointnet: NQ=8 quarters (1024 blocks of 128 pts), 3 CTAs/SM.
//  * k_deform: grid (640,6), one output row per thread.
// ---------------------------------------------------------------------------

#define B_      64
#define S_      1024
#define D_      256
#define KRET    10
#define NPART   16
#define NPAR    96
#define PSRC3   1536
#define NQ      8

__device__ float g_pool[NQ * 2 * B_ * D_];
__device__ float g_ret [B_ * D_];
__device__ float g_T   [B_ * D_];
__device__ int   g_idx [B_ * KRET];
__device__ float g_par [B_ * KRET * NPAR];
__device__ float g_SC1 [S_ * D_];              // 1 MB
__device__ float g_P1  [S_ * NPART * D_];      // 16.8 MB

typedef unsigned long long u64;

__device__ __forceinline__ u64 pk(float lo, float hi) {
    u64 r; asm("mov.b64 %0,{%1,%2};" : "=l"(r) : "f"(lo), "f"(hi)); return r;
}
__device__ __forceinline__ void upk(u64 v, float& lo, float& hi) {
    asm("mov.b64 {%0,%1},%2;" : "=f"(lo), "=f"(hi) : "l"(v));
}
__device__ __forceinline__ u64 fma2(u64 a, u64 b, u64 c) {
    u64 d; asm("fma.rn.f32x2 %0,%1,%2,%3;" : "=l"(d) : "l"(a), "l"(b), "l"(c)); return d;
}

// ---------------------------------------------------------------------------
// Kernel 0: per-source precompute. grid 1024, 256 threads.
// ---------------------------------------------------------------------------
__global__ __launch_bounds__(256, 4)
void k_pre(const float* __restrict__ src_codes,
           const float* __restrict__ part_latent,
           const float* __restrict__ decW1, const float* __restrict__ decb1)
{
    const int s = blockIdx.x, t = threadIdx.x;
    __shared__ float scs[256];
    __shared__ float part[NPART][32];

    scs[t] = src_codes[s * 256 + t];
    ((float*)part)[t]       = part_latent[s * (NPART * 32) + t];
    ((float*)part)[t + 256] = part_latent[s * (NPART * 32) + t + 256];
    __syncthreads();

    // SC1[s][t] = b1[t] + sum_i scs[i] * W1[(256+i)][t]
    {
        float v = decb1[t];
        #pragma unroll 8
        for (int i = 0; i < 256; ++i)
            v = fmaf(scs[i], decW1[(256 + i) * 256 + t], v);
        g_SC1[s * 256 + t] = v;
    }

    // P1[s][p][t] = sum_i part[p][i] * W1[(512+i)][t]
    float wt[32];
    #pragma unroll
    for (int i = 0; i < 32; ++i)
        wt[i] = decW1[(512 + i) * 256 + t];
    #pragma unroll 2
    for (int p = 0; p < NPART; ++p) {
        float v = 0.f;
        #pragma unroll
        for (int i = 0; i < 32; ++i)
            v = fmaf(part[p][i], wt[i], v);
        g_P1[(s * NPART + p) * 256 + t] = v;
    }
}

// ---------------------------------------------------------------------------
// Kernel 1: PointNet encoders, grid (64, 2, NQ), 256 threads, 3 CTAs/SM.
// Each block handles 128 points (4 tiles of 32).
// ---------------------------------------------------------------------------
#define TP 32

__global__ __launch_bounds__(256, 3)
void k_pointnet(const float* __restrict__ noc,
                const float* __restrict__ teW1, const float* __restrict__ teb1,
                const float* __restrict__ teW2, const float* __restrict__ teb2,
                const float* __restrict__ teW3, const float* __restrict__ teb3,
                const float* __restrict__ reW1, const float* __restrict__ reb1,
                const float* __restrict__ reW2, const float* __restrict__ reb2,
                const float* __restrict__ reW3, const float* __restrict__ reb3)
{
    const int b = blockIdx.x;
    const int enc = blockIdx.y;
    const int qz = blockIdx.z;
    const float* W1 = enc ? reW1 : teW1; const float* b1 = enc ? reb1 : teb1;
    const float* W2 = enc ? reW2 : teW2; const float* b2 = enc ? reb2 : teb2;
    const float* W3 = enc ? reW3 : teW3; const float* b3 = enc ? reb3 : teb3;

    __shared__ __align__(16) float X[3][TP];
    __shared__ __align__(16) float H1c[64][34];
    __shared__ __align__(16) float H2c[128][34];
    __shared__ __align__(16) float red[4][256];

    const int t = threadIdx.x;

    const int colB = t & 63, pgB = t >> 6;
    const int c0C = (t & 31) * 4, pgC = t >> 5;
    const int c0D = (t & 63) * 4, pgD = t >> 6;

    const float w10 = W1[colB], w11 = W1[64 + colB], w12 = W1[128 + colB];
    const float bb1 = b1[colB];
    const float4 bb2 = *(const float4*)&b2[c0C];
    const u64 bb2p[4] = { pk(bb2.x, bb2.x), pk(bb2.y, bb2.y),
                          pk(bb2.z, bb2.z), pk(bb2.w, bb2.w) };
    const float b3v[4] = { b3[c0D], b3[c0D+1], b3[c0D+2], b3[c0D+3] };

    float tmax[4] = {0.f, 0.f, 0.f, 0.f};

    for (int tile = 0; tile < 128 / TP; ++tile) {
        __syncthreads();
        if (t < 96) {
            int c = t >> 5, p = t & 31;
            X[c][p] = noc[b * 3072 + c * 1024 + qz * 128 + tile * TP + p];
        }
        __syncthreads();

        // ---- H1: 3 -> 64 ----
        {
            float v[8];
            #pragma unroll
            for (int pp = 0; pp < 8; ++pp) {
                int p = pgB * 8 + pp;
                float h = fmaf(X[0][p], w10, fmaf(X[1][p], w11, fmaf(X[2][p], w12, bb1)));
                v[pp] = fmaxf(h, 0.f);
            }
            #pragma unroll
            for (int q = 0; q < 4; ++q)
                *(u64*)&H1c[colB][pgB * 8 + 2 * q] = pk(v[2*q], v[2*q+1]);
        }
        __syncthreads();

        // ---- H2: 64 -> 128, f32x2 ----
        {
            u64 acc[2][4];
            #pragma unroll
            for (int q = 0; q < 2; ++q)
                #pragma unroll
                for (int j = 0; j < 4; ++j) acc[q][j] = bb2p[j];
            #pragma unroll 4
            for (int k = 0; k < 64; ++k) {
                u64 x0 = *(const u64*)&H1c[k][pgC * 4];
                u64 x1 = *(const u64*)&H1c[k][pgC * 4 + 2];
                float4 w = *(const float4*)&W2[k * 128 + c0C];
                u64 wp0 = pk(w.x, w.x), wp1 = pk(w.y, w.y);
                u64 wp2 = pk(w.z, w.z), wp3 = pk(w.w, w.w);
                acc[0][0] = fma2(x0, wp0, acc[0][0]);
                acc[0][1] = fma2(x0, wp1, acc[0][1]);
                acc[0][2] = fma2(x0, wp2, acc[0][2]);
                acc[0][3] = fma2(x0, wp3, acc[0][3]);
                acc[1][0] = fma2(x1, wp0, acc[1][0]);
                acc[1][1] = fma2(x1, wp1, acc[1][1]);
                acc[1][2] = fma2(x1, wp2, acc[1][2]);
                acc[1][3] = fma2(x1, wp3, acc[1][3]);
            }
            #pragma unroll
            for (int j = 0; j < 4; ++j) {
                #pragma unroll
                for (int q = 0; q < 2; ++q) {
                    float lo, hi; upk(acc[q][j], lo, hi);
                    lo = fmaxf(lo, 0.f); hi = fmaxf(hi, 0.f);
                    *(u64*)&H2c[c0C + j][pgC * 4 + 2 * q] = pk(lo, hi);
                }
            }
        }
        __syncthreads();

        // ---- H3: 128 -> 256, f32x2, bias+relu+running max ----
        {
            u64 acc[4][4];
            #pragma unroll
            for (int q = 0; q < 4; ++q)
                #pragma unroll
                for (int j = 0; j < 4; ++j) acc[q][j] = 0ull;
            #pragma unroll 2
            for (int k = 0; k < 128; ++k) {
                u64 x0 = *(const u64*)&H2c[k][pgD * 8];
                u64 x1 = *(const u64*)&H2c[k][pgD * 8 + 2];
                u64 x2 = *(const u64*)&H2c[k][pgD * 8 + 4];
                u64 x3 = *(const u64*)&H2c[k][pgD * 8 + 6];
                float4 w = *(const float4*)&W3[k * 256 + c0D];
                u64 wp0 = pk(w.x, w.x), wp1 = pk(w.y, w.y);
                u64 wp2 = pk(w.z, w.z), wp3 = pk(w.w, w.w);
                acc[0][0] = fma2(x0, wp0, acc[0][0]);
                acc[0][1] = fma2(x0, wp1, acc[0][1]);
                acc[0][2] = fma2(x0, wp2, acc[0][2]);
                acc[0][3] = fma2(x0, wp3, acc[0][3]);
                acc[1][0] = fma2(x1, wp0, acc[1][0]);
                acc[1][1] = fma2(x1, wp1, acc[1][1]);
                acc[1][2] = fma2(x1, wp2, acc[1][2]);
                acc[1][3] = fma2(x1, wp3, acc[1][3]);
                acc[2][0] = fma2(x2, wp0, acc[2][0]);
                acc[2][1] = fma2(x2, wp1, acc[2][1]);
                acc[2][2] = fma2(x2, wp2, acc[2][2]);
                acc[2][3] = fma2(x2, wp3, acc[2][3]);
                acc[3][0] = fma2(x3, wp0, acc[3][0]);
                acc[3][1] = fma2(x3, wp1, acc[3][1]);
                acc[3][2] = fma2(x3, wp2, acc[3][2]);
                acc[3][3] = fma2(x3, wp3, acc[3][3]);
            }
            #pragma unroll
            for (int q = 0; q < 4; ++q) {
                #pragma unroll
                for (int j = 0; j < 4; ++j) {
                    float lo, hi; upk(acc[q][j], lo, hi);
                    tmax[j] = fmaxf(tmax[j], fmaxf(lo + b3v[j], 0.f));
                    tmax[j] = fmaxf(tmax[j], fmaxf(hi + b3v[j], 0.f));
                }
            }
        }
    }

    #pragma unroll
    for (int j = 0; j < 4; ++j) red[pgD][c0D + j] = tmax[j];
    __syncthreads();
    float m = fmaxf(fmaxf(red[0][t], red[1][t]), fmaxf(red[2][t], red[3][t]));
    g_pool[((qz * 2 + enc) * B_ + b) * D_ + t] = m;
}

// ---------------------------------------------------------------------------
// Kernel 2: reduce quarters + final fc + T = tgt @ dec_W1[0:256]
// ---------------------------------------------------------------------------
__global__ __launch_bounds__(256, 1)
void k_fc(const float* __restrict__ teWf, const float* __restrict__ tebf,
          const float* __restrict__ reWf, const float* __restrict__ rebf,
          const float* __restrict__ decW1)
{
    const int b = blockIdx.x, t = threadIdx.x;
    __shared__ float ste[256], sre[256], stgt[256];
    float mte = 0.f, mre = 0.f;
    #pragma unroll
    for (int q = 0; q < NQ; ++q) {
        mte = fmaxf(mte, g_pool[((q * 2 + 0) * B_ + b) * D_ + t]);
        mre = fmaxf(mre, g_pool[((q * 2 + 1) * B_ + b) * D_ + t]);
    }
    ste[t] = mte; sre[t] = mre;
    __syncthreads();

    float a = tebf[t], r = rebf[t];
    #pragma unroll 8
    for (int i = 0; i < 256; ++i) {
        a = fmaf(ste[i], teWf[i * 256 + t], a);
        r = fmaf(sre[i], reWf[i * 256 + t], r);
    }
    g_ret[b * D_ + t] = r;
    stgt[t] = a;
    __syncthreads();

    float tv = 0.f;
    #pragma unroll 8
    for (int i = 0; i < 256; ++i)
        tv = fmaf(stgt[i], decW1[i * 256 + t], tv);
    g_T[b * D_ + t] = tv;
}

// ---------------------------------------------------------------------------
// Kernel 3: variance-weighted distances + exact top-10
// ---------------------------------------------------------------------------
__global__ __launch_bounds__(256, 1)
void k_dist(const float* __restrict__ rsc, const float* __restrict__ var)
{
    const int b = blockIdx.x, t = threadIdx.x;
    const int lane = t & 31, w = t >> 5;
    __shared__ float rets[256];
    __shared__ float d[1024];
    __shared__ float sval[256];
    __shared__ int   sidx[256];

    rets[t] = g_ret[b * D_ + t];
    __syncthreads();

    for (int s = w; s < S_; s += 8) {
        float p = 0.f;
        #pragma unroll
        for (int q = 0; q < 2; ++q) {
            int k = lane * 8 + q * 4;
            float4 v  = *(const float4*)&var[s * 256 + k];
            float4 rc = *(const float4*)&rsc[s * 256 + k];
            float d0 = rets[k]     - rc.x;
            float d1 = rets[k + 1] - rc.y;
            float d2 = rets[k + 2] - rc.z;
            float d3 = rets[k + 3] - rc.w;
            p = fmaf(v.x, d0 * d0, p);
            p = fmaf(v.y, d1 * d1, p);
            p = fmaf(v.z, d2 * d2, p);
            p = fmaf(v.w, d3 * d3, p);
        }
        #pragma unroll
        for (int off = 16; off > 0; off >>= 1)
            p += __shfl_xor_sync(0xffffffffu, p, off);
        if (lane == 0) d[s] = p;
    }
    __syncthreads();

    for (int it = 0; it < KRET; ++it) {
        float bv = 1e30f; int bi = S_;
        #pragma unroll
        for (int q = 0; q < 4; ++q) {
            int s = q * 256 + t;
            float v = d[s];
            if (v < bv || (v == bv && s < bi)) { bv = v; bi = s; }
        }
        sval[t] = bv; sidx[t] = bi;
        __syncthreads();
        for (int off = 128; off > 0; off >>= 1) {
            if (t < off) {
                float v2 = sval[t + off]; int i2 = sidx[t + off];
                if (v2 < sval[t] || (v2 == sval[t] && i2 < sidx[t])) {
                    sval[t] = v2; sidx[t] = i2;
                }
            }
            __syncthreads();
        }
        if (t == 0) {
            g_idx[b * KRET + it] = sidx[0];
            d[sidx[0]] = 1e30f;
        }
        __syncthreads();
    }
}

// ---------------------------------------------------------------------------
// Kernel 4: decoder MLP -> params[96] per (b,k). 4 CTAs/SM.
// smem activation layout: u64 [chan][pairOfParts], i.e. float [chan][18].
// ---------------------------------------------------------------------------
__global__ __launch_bounds__(256, 4)
void k_decode_mlp(const float* __restrict__ decW2, const float* __restrict__ decb2,
                  const float* __restrict__ decW3, const float* __restrict__ decb3,
                  const float* __restrict__ proj,  const float* __restrict__ defp)
{
    const int bk = blockIdx.x;
    const int b = bk / KRET;
    const int t = threadIdx.x;
    const int s = g_idx[bk];

    __shared__ __align__(16) u64 H1p[256][9];
    __shared__ __align__(16) u64 H2p[256][9];
    __shared__ float raw[NPAR];

    // ---- layer 1: H1[p][c] = relu(T[b][c] + SC1[s][c] + P1[s][p][c]) ----
    {
        float base = g_T[b * D_ + t] + g_SC1[s * 256 + t];
        const float* p1 = &g_P1[s * (NPART * 256) + t];
        #pragma unroll
        for (int pr = 0; pr < 8; ++pr) {
            float lo = fmaxf(base + p1[(2 * pr) * 256], 0.f);
            float hi = fmaxf(base + p1[(2 * pr + 1) * 256], 0.f);
            H1p[t][pr] = pk(lo, hi);
        }
    }
    __syncthreads();

    const int c0 = (t & 63) * 4, pg = t >> 6;   // 4 cols x 4 parts (2 pairs)

    // ---- H2: 256 -> 256, f32x2 over part pairs ----
    {
        u64 acc[2][4];
        float4 bb = *(const float4*)&decb2[c0];
        acc[0][0] = acc[1][0] = pk(bb.x, bb.x);
        acc[0][1] = acc[1][1] = pk(bb.y, bb.y);
        acc[0][2] = acc[1][2] = pk(bb.z, bb.z);
        acc[0][3] = acc[1][3] = pk(bb.w, bb.w);
        #pragma unroll 4
        for (int k = 0; k < 256; ++k) {
            u64 x0 = H1p[k][pg * 2];
            u64 x1 = H1p[k][pg * 2 + 1];
            float4 w = *(const float4*)&decW2[k * 256 + c0];
            u64 wp0 = pk(w.x, w.x), wp1 = pk(w.y, w.y);
            u64 wp2 = pk(w.z, w.z), wp3 = pk(w.w, w.w);
            acc[0][0] = fma2(x0, wp0, acc[0][0]);
            acc[0][1] = fma2(x0, wp1, acc[0][1]);
            acc[0][2] = fma2(x0, wp2, acc[0][2]);
            acc[0][3] = fma2(x0, wp3, acc[0][3]);
            acc[1][0] = fma2(x1, wp0, acc[1][0]);
            acc[1][1] = fma2(x1, wp1, acc[1][1]);
            acc[1][2] = fma2(x1, wp2, acc[1][2]);
            acc[1][3] = fma2(x1, wp3, acc[1][3]);
        }
        #pragma unroll
        for (int j = 0; j < 4; ++j) {
            #pragma unroll
            for (int q = 0; q < 2; ++q) {
                float lo, hi; upk(acc[q][j], lo, hi);
                lo = fmaxf(lo, 0.f); hi = fmaxf(hi, 0.f);
                H2p[c0 + j][pg * 2 + q] = pk(lo, hi);
            }
        }
    }
    __syncthreads();

    // ---- raw = H2 @ W3 + b3 ----
    const float* H2f = (const float*)H2p;   // [k][18], part p at H2f[k*18+p]
    if (t < NPAR) {
        const int p = t / 6, o = t % 6;
        float v = decb3[o];
        #pragma unroll 8
        for (int k = 0; k < 256; ++k)
            v = fmaf(H2f[k * 18 + p], decW3[k * 6 + o], v);
        raw[t] = v;
    }
    __syncthreads();

    // ---- params = proj[s] @ raw + def[s] -> g_par ----
    if (t < NPAR) {
        float v = defp[s * NPAR + t];
        const float* pr = proj + (size_t)s * NPAR * NPAR + t * NPAR;
        #pragma unroll 8
        for (int j = 0; j < NPAR; ++j)
            v = fmaf(pr[j], raw[j], v);
        g_par[bk * NPAR + t] = v;
    }
}

// ---------------------------------------------------------------------------
// Kernel 5: deformation pts = mat[s] @ params. grid (640, 6), L2-BW bound.
// ---------------------------------------------------------------------------
__global__ __launch_bounds__(256)
void k_deform(const float* __restrict__ mat, float* __restrict__ out)
{
    const int bk = blockIdx.x;
    const int t = threadIdx.x;
    const int s = g_idx[bk];
    __shared__ float par[NPAR];
    if (t < NPAR) par[t] = g_par[bk * NPAR + t];
    __syncthreads();

    const int r = blockIdx.y * 256 + t;
    const float* mr = mat + (size_t)s * PSRC3 * NPAR + (size_t)r * NPAR;
    float v = 0.f;
    #pragma unroll
    for (int j4 = 0; j4 < 24; ++j4) {
        float4 m4 = *(const float4*)&mr[j4 * 4];
        v = fmaf(m4.x, par[j4 * 4 + 0], v);
        v = fmaf(m4.y, par[j4 * 4 + 1], v);
        v = fmaf(m4.z, par[j4 * 4 + 2], v);
        v = fmaf(m4.w, par[j4 * 4 + 3], v);
    }
    out[(size_t)bk * PSRC3 + r] = v;
}

// ---------------------------------------------------------------------------
extern "C" void kernel_launch(void* const* d_in, const int* in_sizes, int n_in,
                              void* d_out, int out_size)
{
    const float* noc  = (const float*)d_in[0];
    const float* teW1 = (const float*)d_in[1];  const float* teb1 = (const float*)d_in[2];
    const float* teW2 = (const float*)d_in[3];  const float* teb2 = (const float*)d_in[4];
    const float* teW3 = (const float*)d_in[5];  const float* teb3 = (const float*)d_in[6];
    const float* teWf = (const float*)d_in[7];  const float* tebf = (const float*)d_in[8];
    const float* reW1 = (const float*)d_in[9];  const float* reb1 = (const float*)d_in[10];
    const float* reW2 = (const float*)d_in[11]; const float* reb2 = (const float*)d_in[12];
    const float* reW3 = (const float*)d_in[13]; const float* reb3 = (const float*)d_in[14];
    const float* reWf = (const float*)d_in[15]; const float* rebf = (const float*)d_in[16];
    const float* decW1 = (const float*)d_in[17]; const float* decb1 = (const float*)d_in[18];
    const float* decW2 = (const float*)d_in[19]; const float* decb2 = (const float*)d_in[20];
    const float* decW3 = (const float*)d_in[21]; const float* decb3 = (const float*)d_in[22];
    const float* ret_src = (const float*)d_in[23];
    const float* src_codes = (const float*)d_in[24];
    const float* src_var = (const float*)d_in[25];
    const float* part_latent = (const float*)d_in[26];
    const float* defp = (const float*)d_in[27];
    const float* proj = (const float*)d_in[28];
    const float* mat  = (const float*)d_in[29];
    float* out = (float*)d_out;

    k_pre<<<S_, 256>>>(src_codes, part_latent, decW1, decb1);
    dim3 g1(B_, 2, NQ);
    k_pointnet<<<g1, 256>>>(noc,
                            teW1, teb1, teW2, teb2, teW3, teb3,
                            reW1, reb1, reW2, reb2, reW3, reb3);
    k_fc<<<B_, 256>>>(teWf, tebf, reWf, rebf, decW1);
    k_dist<<<B_, 256>>>(ret_src, src_var);
    k_decode_mlp<<<B_ * KRET, 256>>>(decW2, decb2, decW3, decb3, proj, defp);
    dim3 g5(B_ * KRET, 6);
    k_deform<<<g5, 256>>>(mat, out);
}